// round 7
// baseline (speedup 1.0000x reference)
#include <cuda_runtime.h>
#include <cuda_fp16.h>
#include <cstdint>

// Shapes
#define N_Q    65536
#define DIM    64
#define K_EMB  1024
#define QB     128        // queries per block (8 warps x 16 rows)
#define THREADS 256
#define NBLOCKS (N_Q / QB)   // 512
#define NGROUP 128        // 1024 codes / 8 per n-group
#define PAD    68

#define ESCALE      1024.0f          // exact power-of-2 codebook scaling
#define INV_2SCALE  (1.0f / 512.0f)  // 2*dot = dsum/512 (exact)

#define OUT_QV_ELEMS  (64ULL * 64ULL * 32ULL * 32ULL)   // 4194304
#define OUT_IDX_OFF   4194304ULL
#define OUT_LOSS_OFF  4259840ULL

// device scratch (no cudaMalloc; zero-initialized at module load)
__device__ double   g_partial[NBLOCKS];
__device__ unsigned g_done;   // monotonically increasing; 2^32 % 512 == 0

__device__ __forceinline__ uint32_t pack_h2(__half lo, __half hi) {
    __half2 h = __halves2half2(lo, hi);
    return *reinterpret_cast<uint32_t*>(&h);
}
__device__ __forceinline__ uint32_t cvt_h2(float lo, float hi) {
    __half2 h = __floats2half2_rn(lo, hi);
    return *reinterpret_cast<uint32_t*>(&h);
}

__device__ __forceinline__ void mma_f16(float& d0, float& d1, float& d2, float& d3,
                                        uint32_t a0, uint32_t a1, uint32_t a2, uint32_t a3,
                                        uint32_t b0, uint32_t b1) {
    asm volatile(
        "mma.sync.aligned.m16n8k16.row.col.f32.f16.f16.f32 "
        "{%0,%1,%2,%3}, {%4,%5,%6,%7}, {%8,%9}, {%0,%1,%2,%3};\n"
        : "+f"(d0), "+f"(d1), "+f"(d2), "+f"(d3)
        : "r"(a0), "r"(a1), "r"(a2), "r"(a3), "r"(b0), "r"(b1));
}

// ---------------------------------------------------------------------------
// Single kernel: stage + norms; Phase A hh-fp16 MMA screen (best+second);
// Phase B exact fp32 full rescan for flagged queries; outputs; loss via
// last-block counter.
// ---------------------------------------------------------------------------
__global__ void __launch_bounds__(THREADS, 2)
vq_main(const float* __restrict__ z,
        const float* __restrict__ emb,
        float* __restrict__ out) {
    __shared__ float  sBuf[QB * PAD];   // exact fp32 z tile
    __shared__ float  sSe[K_EMB];
    __shared__ float  sSz[QB];
    __shared__ int    sIdx[QB];
    __shared__ int    sFq[QB];
    __shared__ int    sCnt;
    __shared__ float  sMaxSe[THREADS / 32];
    __shared__ int    sLast;
    __shared__ double sRed[THREADS / 32];

    const int tid  = threadIdx.x;
    const int wid  = tid >> 5;
    const int lane = tid & 31;
    const int gid  = lane >> 2;
    const int tig  = lane & 3;
    const int qb   = blockIdx.x * QB;

    if (tid == 0) { sCnt = 0; sLast = 0; }

    // ---- stage z tile ----
    {
        const float4* src = reinterpret_cast<const float4*>(z + (size_t)qb * DIM);
        #pragma unroll
        for (int i = tid; i < QB * (DIM / 4); i += THREADS) {
            int row = i >> 4, c4 = i & 15;
            float4 v = __ldg(src + row * (DIM / 4) + c4);
            *reinterpret_cast<float4*>(&sBuf[row * PAD + 4 * c4]) = v;
        }
    }

    // ---- se2 for all codes (square-then-add sequential), per block ----
    float myMax = 0.0f;
    #pragma unroll
    for (int c = tid; c < K_EMB; c += THREADS) {
        const float4* e4 = reinterpret_cast<const float4*>(emb + (size_t)c * DIM);
        float s = 0.0f;
        #pragma unroll
        for (int j = 0; j < DIM / 4; ++j) {
            float4 e = __ldg(e4 + j);
            s = __fadd_rn(s, __fmul_rn(e.x, e.x));
            s = __fadd_rn(s, __fmul_rn(e.y, e.y));
            s = __fadd_rn(s, __fmul_rn(e.z, e.z));
            s = __fadd_rn(s, __fmul_rn(e.w, e.w));
        }
        sSe[c] = s;
        myMax = fmaxf(myMax, s);
    }
    // block max of se2 -> maxE = 1024*sqrt(max)
    #pragma unroll
    for (int off = 16; off > 0; off >>= 1)
        myMax = fmaxf(myMax, __shfl_xor_sync(0xFFFFFFFFu, myMax, off));
    if (lane == 0) sMaxSe[wid] = myMax;
    __syncthreads();

    // row norms (square-then-add, sequential; reference style)
    if (tid < QB) {
        const float* r = &sBuf[tid * PAD];
        float s = 0.0f;
        #pragma unroll
        for (int j = 0; j < DIM; ++j)
            s = __fadd_rn(s, __fmul_rn(r[j], r[j]));
        sSz[tid] = s;
    }
    __syncthreads();

    float mTmp = sMaxSe[lane & 7];
    #pragma unroll
    for (int off = 4; off > 0; off >>= 1)
        mTmp = fmaxf(mTmp, __shfl_xor_sync(0xFFFFFFFFu, mTmp, off));
    const float maxE = sqrtf(mTmp) * ESCALE;   // uniform across warp

    // ---- A fragments (fp16 hi only), rows r0=wid*16+gid, r1=r0+8 ----
    uint32_t aH[4][4];
    const int r0 = wid * 16 + gid;
    const int r1 = r0 + 8;
    #pragma unroll
    for (int s = 0; s < 4; ++s) {
        const int k = s * 16 + tig * 2;
        aH[s][0] = cvt_h2(sBuf[r0 * PAD + k],     sBuf[r0 * PAD + k + 1]);
        aH[s][1] = cvt_h2(sBuf[r1 * PAD + k],     sBuf[r1 * PAD + k + 1]);
        aH[s][2] = cvt_h2(sBuf[r0 * PAD + k + 8], sBuf[r0 * PAD + k + 9]);
        aH[s][3] = cvt_h2(sBuf[r1 * PAD + k + 8], sBuf[r1 * PAD + k + 9]);
    }
    const float sz0 = sSz[r0];
    const float sz1 = sSz[r1];

    // ---- Phase A: hh screen with best + second-best tracking ----
    float b0 = 3.4e38f, s0v = 3.4e38f; int i0 = 0;
    float b1 = 3.4e38f, s1v = 3.4e38f; int i1 = 0;

    // B fragments converted inline from fp32 emb (L2-resident).
    const float2* e2 = reinterpret_cast<const float2*>(emb);
    #pragma unroll 2
    for (int g = 0; g < NGROUP; ++g) {
        const int code = g * 8 + gid;
        const float2* erow = e2 + code * (DIM / 2);
        float d0 = 0.f, d1 = 0.f, d2 = 0.f, d3 = 0.f;
        #pragma unroll
        for (int s = 0; s < 4; ++s) {
            float2 lo = __ldg(erow + s * 8 + tig);
            float2 hi = __ldg(erow + s * 8 + tig + 4);
            uint32_t bb0 = cvt_h2(lo.x * ESCALE, lo.y * ESCALE);
            uint32_t bb1 = cvt_h2(hi.x * ESCALE, hi.y * ESCALE);
            mma_f16(d0, d1, d2, d3, aH[s][0], aH[s][1], aH[s][2], aH[s][3], bb0, bb1);
        }

        const int c0 = g * 8 + 2 * tig;
        const float se0 = sSe[c0], se1 = sSe[c0 + 1];
        const float q00 = sz0 - d0 * INV_2SCALE + se0;
        const float q01 = sz0 - d1 * INV_2SCALE + se1;
        const float q10 = sz1 - d2 * INV_2SCALE + se0;
        const float q11 = sz1 - d3 * INV_2SCALE + se1;

        if (q00 < b0) { s0v = b0; b0 = q00; i0 = c0; }     else if (q00 < s0v) s0v = q00;
        if (q01 < b0) { s0v = b0; b0 = q01; i0 = c0 + 1; } else if (q01 < s0v) s0v = q01;
        if (q10 < b1) { s1v = b1; b1 = q10; i1 = c0; }     else if (q10 < s1v) s1v = q10;
        if (q11 < b1) { s1v = b1; b1 = q11; i1 = c0 + 1; } else if (q11 < s1v) s1v = q11;
    }

    // ---- quad butterfly reduce (best, idx, second) per row ----
    #pragma unroll
    for (int off = 1; off <= 2; off <<= 1) {
        float ob = __shfl_xor_sync(0xFFFFFFFFu, b0, off);
        int   oi = __shfl_xor_sync(0xFFFFFFFFu, i0, off);
        float os = __shfl_xor_sync(0xFFFFFFFFu, s0v, off);
        if (ob < b0) { s0v = fminf(b0, os); b0 = ob; i0 = oi; }
        else         { s0v = fminf(s0v, ob); }
        float ob1 = __shfl_xor_sync(0xFFFFFFFFu, b1, off);
        int   oi1 = __shfl_xor_sync(0xFFFFFFFFu, i1, off);
        float os1 = __shfl_xor_sync(0xFFFFFFFFu, s1v, off);
        if (ob1 < b1) { s1v = fminf(b1, os1); b1 = ob1; i1 = oi1; }
        else          { s1v = fminf(s1v, ob1); }
    }

    if (tig == 0) {
        sIdx[r0] = i0;
        sIdx[r1] = i1;
        // rigorous rescue margin: 2*err(2dot) + accumulation/epilogue slack
        const float m0 = sqrtf(sz0) * maxE * 4.0e-6f + 1.2e-4f;
        const float m1 = sqrtf(sz1) * maxE * 4.0e-6f + 1.2e-4f;
        if (s0v - b0 <= m0) { int p = atomicAdd(&sCnt, 1); sFq[p] = r0; }
        if (s1v - b1 <= m1) { int p = atomicAdd(&sCnt, 1); sFq[p] = r1; }
    }
    __syncthreads();

    // ---- Phase B: exact fp32 full rescan (reference rounding), warp/query ----
    const int cnt = sCnt;
    for (int f = wid; f < cnt; f += THREADS / 32) {
        const int q = sFq[f];
        const float szq = sSz[q];
        const float4* zq4 = reinterpret_cast<const float4*>(&sBuf[q * PAD]);
        float best = 3.4e38f; int bi = 0;
        for (int c = lane; c < K_EMB; c += 32) {
            const float4* e4 = reinterpret_cast<const float4*>(emb + (size_t)c * DIM);
            float a0 = 0.f, a1 = 0.f, a2 = 0.f, a3 = 0.f;
            #pragma unroll
            for (int j = 0; j < DIM / 4; ++j) {
                float4 e = __ldg(e4 + j);
                float4 zv = zq4[j];            // broadcast LDS.128
                a0 = fmaf(zv.x, e.x, a0);
                a1 = fmaf(zv.y, e.y, a1);
                a2 = fmaf(zv.z, e.z, a2);
                a3 = fmaf(zv.w, e.w, a3);
            }
            float dot = __fadd_rn(__fadd_rn(a0, a1), __fadd_rn(a2, a3));
            float d2 = __fadd_rn(__fsub_rn(szq, __fmul_rn(2.0f, dot)), sSe[c]);
            if (d2 < best) { best = d2; bi = c; }   // ascending c: first-index
        }
        #pragma unroll
        for (int off = 16; off > 0; off >>= 1) {
            float ov = __shfl_down_sync(0xFFFFFFFFu, best, off);
            int   oi = __shfl_down_sync(0xFFFFFFFFu, bi, off);
            if (ov < best || (ov == best && oi < bi)) { best = ov; bi = oi; }
        }
        if (lane == 0) sIdx[q] = bi;
    }
    __syncthreads();

    // ---- outputs: gather, STE, idx, loss partial ----
    double lsum = 0.0;
    if (tid < QB) {
        const int n = qb + tid;
        const int bidx = sIdx[tid];
        const int w = n & 31;
        const int h = (n >> 5) & 31;
        const int b = n >> 10;
        const size_t obase = (size_t)b * 65536 + (size_t)h * 32 + w;

        const float4* zrow = reinterpret_cast<const float4*>(z + (size_t)n * DIM);
        const float*  eb   = emb + (size_t)bidx * DIM;
        #pragma unroll
        for (int i4 = 0; i4 < DIM / 4; ++i4) {
            float4 zq4 = __ldg(zrow + i4);
            float zq[4] = {zq4.x, zq4.y, zq4.z, zq4.w};
            #pragma unroll
            for (int j = 0; j < 4; ++j) {
                const int d = 4 * i4 + j;
                float q = __ldg(eb + d);
                float diff = __fsub_rn(q, zq[j]);
                out[obase + (size_t)d * 1024] = __fadd_rn(zq[j], diff);  // STE
                lsum += (double)diff * (double)diff;
            }
        }
        out[OUT_IDX_OFF + (size_t)n] = (float)bidx;
    }

    // ---- block loss reduction + last-block finalize ----
    #pragma unroll
    for (int off = 16; off > 0; off >>= 1)
        lsum += __shfl_down_sync(0xFFFFFFFFu, lsum, off);
    if (lane == 0) sRed[wid] = lsum;
    __syncthreads();
    if (tid == 0) {
        double v = 0.0;
        #pragma unroll
        for (int i = 0; i < THREADS / 32; ++i) v += sRed[i];
        g_partial[blockIdx.x] = v;
        __threadfence();
        unsigned old = atomicAdd(&g_done, 1u);
        if ((old & (NBLOCKS - 1)) == (NBLOCKS - 1)) sLast = 1;
    }
    __syncthreads();

    if (sLast && wid == 0) {
        __threadfence();
        double v = 0.0;
        #pragma unroll
        for (int i = 0; i < NBLOCKS / 32; ++i)      // fixed order: deterministic
            v += g_partial[lane + i * 32];
        #pragma unroll
        for (int off = 16; off > 0; off >>= 1)
            v += __shfl_down_sync(0xFFFFFFFFu, v, off);
        if (lane == 0) {
            double mean = v / (double)OUT_QV_ELEMS;
            out[OUT_LOSS_OFF] = (float)(mean * 0.25 + mean * 1.0);
        }
    }
}

extern "C" void kernel_launch(void* const* d_in, const int* in_sizes, int n_in,
                              void* d_out, int out_size) {
    const float* z   = (const float*)d_in[0];
    const float* emb = (const float*)d_in[1];
    float* out = (float*)d_out;

    vq_main<<<NBLOCKS, THREADS>>>(z, emb, out);
}